// round 17
// baseline (speedup 1.0000x reference)
#include <cuda_runtime.h>

#define N 8192
#define THREADS 256
#define ROWS_PER_BLOCK 8
#define KCHUNK 1024
#define NCHUNK (N / KCHUNK)                 // 8
#define ROWGROUPS (N / ROWS_PER_BLOCK)      // 1024
#define WORK_GRID (ROWGROUPS * NCHUNK)      // 8192
#define POLL_BLOCKS 32
#define GRID (WORK_GRID + POLL_BLOCKS)
#define ITERS (KCHUNK / (32 * 4))           // 8 float4 iters per lane
#define TARGET (NCHUNK * ROWS_PER_BLOCK)    // 64 warp-arrivals per rowgroup

__device__ float g_part[NCHUNK * N];
__device__ unsigned int g_cnt[ROWGROUPS];   // zero-init; pollers reset to 0

__device__ __forceinline__ float fast_tanh(float v)
{
    float o;
    asm("tanh.approx.f32 %0, %1;" : "=f"(o) : "f"(v));
    return o;
}

__device__ __forceinline__ void red_release_add(unsigned int* p, unsigned int v)
{
    asm volatile("red.release.gpu.global.add.u32 [%0], %1;"
                 :: "l"(p), "r"(v) : "memory");
}

__device__ __forceinline__ unsigned int ld_acquire(const unsigned int* p)
{
    unsigned int v;
    asm volatile("ld.acquire.gpu.global.u32 %0, [%1];"
                 : "=r"(v) : "l"(p) : "memory");
    return v;
}

__global__ __launch_bounds__(THREADS) void gemv_fused_kernel(
    const float* __restrict__ x,
    const float* __restrict__ y,
    const float* __restrict__ W,
    float* __restrict__ out)
{
    const int tid = threadIdx.x;
    const int bx  = blockIdx.x;

    if (bx >= WORK_GRID) {
        // ---- Poller block: finalize 256 rows during the drain phase. ----
        const int row  = (bx - WORK_GRID) * 256 + tid;
        const int rowg = row >> 3;

        float xi = x[row];    // GEMV-independent prefetch
        float yi = y[row];

        if ((tid & 7) == 0) {
            while (ld_acquire(&g_cnt[rowg]) != TARGET)
                __nanosleep(64);
        }
        __syncwarp();

        // 8 partials, fixed order, L1-bypassing loads (written via __stcg).
        float acc = ((__ldcg(&g_part[0 * N + row]) + __ldcg(&g_part[1 * N + row]))
                   + (__ldcg(&g_part[2 * N + row]) + __ldcg(&g_part[3 * N + row])))
                  + ((__ldcg(&g_part[4 * N + row]) + __ldcg(&g_part[5 * N + row]))
                   + (__ldcg(&g_part[6 * N + row]) + __ldcg(&g_part[7 * N + row])));
        const float DT  = 1e-3f;
        const float TAU = 1e-2f;
        out[row] = yi + DT * ((-yi + acc + xi) / TAU);

        __syncwarp();
        if ((tid & 7) == 0)
            g_cnt[rowg] = 0u;   // reset for next graph replay
        return;
    }

    // ---- Worker block: unchanged R16 GEMV body. ----
    __shared__ float r_s[KCHUNK];  // 4 KB

    const int chunk = bx >> 10;          // bx / ROWGROUPS (chunk-major)
    const int rowg  = bx & (ROWGROUPS - 1);
    const int col0  = chunk * KCHUNK;

    {
        const float4* ysrc = reinterpret_cast<const float4*>(y + col0);
        float4* rdst = reinterpret_cast<float4*>(r_s);
        float4 v = ysrc[tid];            // KCHUNK/4 == THREADS
        float4 t;
        t.x = fast_tanh(v.x); t.y = fast_tanh(v.y);
        t.z = fast_tanh(v.z); t.w = fast_tanh(v.w);
        rdst[tid] = t;
    }
    __syncthreads();

    const int warp = tid >> 5;
    const int lane = tid & 31;
    const int row  = rowg * ROWS_PER_BLOCK + warp;

    const float4* __restrict__ Wrow =
        reinterpret_cast<const float4*>(W + (size_t)row * N + col0);
    const float4* rs4 = reinterpret_cast<const float4*>(r_s);

    float a0 = 0.f, a1 = 0.f, a2 = 0.f, a3 = 0.f;
    #pragma unroll
    for (int i = 0; i < ITERS; i += 4) {
        float4 w0 = Wrow[(i + 0) * 32 + lane];
        float4 w1 = Wrow[(i + 1) * 32 + lane];
        float4 w2 = Wrow[(i + 2) * 32 + lane];
        float4 w3 = Wrow[(i + 3) * 32 + lane];
        float4 v0 = rs4[(i + 0) * 32 + lane];
        float4 v1 = rs4[(i + 1) * 32 + lane];
        float4 v2 = rs4[(i + 2) * 32 + lane];
        float4 v3 = rs4[(i + 3) * 32 + lane];
        a0 += w0.x * v0.x + w0.y * v0.y + w0.z * v0.z + w0.w * v0.w;
        a1 += w1.x * v1.x + w1.y * v1.y + w1.z * v1.z + w1.w * v1.w;
        a2 += w2.x * v2.x + w2.y * v2.y + w2.z * v2.z + w2.w * v2.w;
        a3 += w3.x * v3.x + w3.y * v3.y + w3.z * v3.z + w3.w * v3.w;
    }
    float acc = (a0 + a1) + (a2 + a3);

    #pragma unroll
    for (int off = 16; off > 0; off >>= 1)
        acc += __shfl_xor_sync(0xFFFFFFFFu, acc, off);

    if (lane == 0) {
        __stcg(&g_part[chunk * N + row], acc);
        red_release_add(&g_cnt[rowg], 1u);   // fire-and-forget arrival
    }
    // Warps retire independently — no trailing syncs.
}

extern "C" void kernel_launch(void* const* d_in, const int* in_sizes, int n_in,
                              void* d_out, int out_size)
{
    const float* x = (const float*)d_in[0];
    const float* y = (const float*)d_in[1];
    const float* W = (const float*)d_in[2];
    float* out = (float*)d_out;

    gemv_fused_kernel<<<GRID, THREADS>>>(x, y, W, out);
}